// round 15
// baseline (speedup 1.0000x reference)
#include <cuda_runtime.h>
#include <cuda_bf16.h>

#define SEQ   1024
#define BATCH 512
#define NT    64
#define TPB   64    // one block per batch; thread j = tag j; 2 warps

// Scratch (device globals; no allocation).
__device__ float g_llh[BATCH];
__device__ int   g_done;

__global__ void __launch_bounds__(TPB)
crf_kernel(const float* __restrict__ em,
           const void* __restrict__ tags_raw,
           const int* __restrict__ mask,
           const float* __restrict__ startT,
           const float* __restrict__ endT,
           const float* __restrict__ trans,
           float* __restrict__ out)
{
    const int b    = blockIdx.x;      // one batch per block
    const int j    = threadIdx.x;     // tag 0..63
    const int lane = j & 31;
    const int warp = j >> 5;

    // packed state, double-buffered: shP[buf][i] = (F_i, U_i) in bf16x2
    __shared__ __align__(16) __nv_bfloat162 shP[2][NT];
    __shared__ float sh_red[2];
    __shared__ int   sh_len[2];
    __shared__ int   sh_flag;

    // ---- packed transition coeffs: hT[i] = (exp(T[i][j]), exp(T[j][i])) ----
    __nv_bfloat162 hT[NT];
#pragma unroll
    for (int i = 0; i < NT; ++i)
        hT[i] = __floats2bfloat162_rn(__expf(trans[i * NT + j]),
                                      __expf(trans[j * NT + i]));

    // ---- sequence length (mask monotone: mask[t] = t < length) ----
    int cnt = 0;
#pragma unroll
    for (int t = j; t < SEQ; t += TPB)
        cnt += mask[t * BATCH + b];
#pragma unroll
    for (int o = 16; o > 0; o >>= 1)
        cnt += __shfl_xor_sync(0xffffffffu, cnt, o);
    if (lane == 0) sh_len[warp] = cnt;
    __syncthreads();
    const int length = sh_len[0] + sh_len[1];

    const int m  = (length - 1) >> 1;   // meeting point
    const int nf = m;                   // fwd super-steps
    const int nb = (length - 1) - m;    // bwd steps (= nf or nf+1)

    // ---- numerator ----
    float gnum = 0.f;
    {
        const int*       t32 = (const int*)tags_raw;
        const long long* t64 = (const long long*)tags_raw;
        bool is64 = true;
#pragma unroll
        for (int k = 0; k < 16; ++k)
            is64 = is64 && (t32[2 * k * 1031 + 1] == 0);

        float num = 0.f;
        if (is64) {
            for (int t = 1 + j; t < length; t += TPB) {
                const int pt = (int)t64[(t - 1) * BATCH + b];
                const int ct = (int)t64[t * BATCH + b];
                num += trans[pt * NT + ct] + em[(t * BATCH + b) * NT + ct];
            }
        } else {
            for (int t = 1 + j; t < length; t += TPB) {
                const int pt = t32[(t - 1) * BATCH + b];
                const int ct = t32[t * BATCH + b];
                num += trans[pt * NT + ct] + em[(t * BATCH + b) * NT + ct];
            }
        }
#pragma unroll
        for (int o = 16; o > 0; o >>= 1)
            num += __shfl_xor_sync(0xffffffffu, num, o);
        if (lane == 0) sh_red[warp] = num;
        __syncthreads();
        if (j == 0) {
            const int t0 = is64 ? (int)t64[b] : t32[b];
            const int tl = is64 ? (int)t64[(length - 1) * BATCH + b]
                                : t32[(length - 1) * BATCH + b];
            gnum = sh_red[0] + sh_red[1]
                 + startT[t0] + em[b * NT + t0] + endT[tl];
        }
        __syncthreads();
    }

    // ---- em streams: fwd ascending from row 0, bwd descending from L-1 ----
    const int sV = BATCH * NT;
    const int bF = b * NT + j;                          // fwd base (row 0)
    const int bB = (length - 1) * sV + b * NT + j;      // bwd base

    shP[0][j] = __floats2bfloat162_rn(__expf(startT[j] + em[bF]),
                                      __expf(endT[j] + em[bB]));

    float pf0 = (1 <= nf) ? em[bF + 1 * sV] : 0.f;
    float pf1 = (2 <= nf) ? em[bF + 2 * sV] : 0.f;
    float pf2 = (3 <= nf) ? em[bF + 3 * sV] : 0.f;
    float pf3 = (4 <= nf) ? em[bF + 4 * sV] : 0.f;
    float pb0 = (1 <= nb) ? em[bB - 1 * sV] : 0.f;
    float pb1 = (2 <= nb) ? em[bB - 2 * sV] : 0.f;
    float pb2 = (3 <= nb) ? em[bB - 3 * sV] : 0.f;
    float pb3 = (4 <= nb) ? em[bB - 4 * sV] : 0.f;

    int ktf = 0, ktb = 0;
    __syncthreads();

    const __nv_bfloat162 hz = __floats2bfloat162_rn(0.f, 0.f);

    // Super-step: both directions advance via lane-packed HFMA2.
#define SSTEP(PP, EXF, EXB, RENORM) do {                                     \
        const uint4* __restrict__ e4 = (const uint4*)shP[PP];                 \
        float scF_ = 1.0f, scU_ = 1.0f;                                       \
        if (RENORM) {                                                         \
            const unsigned w0 = *(const unsigned*)&shP[PP][0];                \
            const int kf = (int)((w0 >> 7)  & 0xFFu) - 127;                   \
            const int ku = (int)((w0 >> 23) & 0xFFu) - 127;                   \
            scF_ = __int_as_float((127 - kf) << 23);                          \
            scU_ = __int_as_float((127 - ku) << 23);                          \
            ktf += kf; ktb += ku;                                             \
        }                                                                     \
        __nv_bfloat162 a0 = hz, a1 = hz, a2 = hz, a3 = hz;                    \
        __nv_bfloat162 a4 = hz, a5 = hz, a6 = hz, a7 = hz;                    \
        _Pragma("unroll")                                                     \
        for (int k = 0; k < 8; ++k) {          /* pairs 8k .. 8k+7 */         \
            const uint4 qa = e4[2 * k];                                       \
            const uint4 qb = e4[2 * k + 1];                                   \
            a0 = __hfma2(*(const __nv_bfloat162*)&qa.x, hT[8 * k + 0], a0);   \
            a1 = __hfma2(*(const __nv_bfloat162*)&qa.y, hT[8 * k + 1], a1);   \
            a2 = __hfma2(*(const __nv_bfloat162*)&qa.z, hT[8 * k + 2], a2);   \
            a3 = __hfma2(*(const __nv_bfloat162*)&qa.w, hT[8 * k + 3], a3);   \
            a4 = __hfma2(*(const __nv_bfloat162*)&qb.x, hT[8 * k + 4], a4);   \
            a5 = __hfma2(*(const __nv_bfloat162*)&qb.y, hT[8 * k + 5], a5);   \
            a6 = __hfma2(*(const __nv_bfloat162*)&qb.z, hT[8 * k + 6], a6);   \
            a7 = __hfma2(*(const __nv_bfloat162*)&qb.w, hT[8 * k + 7], a7);   \
        }                                                                     \
        const __nv_bfloat162 s2 =                                             \
            __hadd2(__hadd2(__hadd2(a0, a1), __hadd2(a2, a3)),                \
                    __hadd2(__hadd2(a4, a5), __hadd2(a6, a7)));               \
        const float2 f = __bfloat1622float2(s2);                              \
        const float nF = f.x * ((EXF) * scF_);                                \
        const float nU = f.y * ((EXB) * scU_);                                \
        shP[(PP) ^ 1][j] = __floats2bfloat162_rn(nF, nU);                     \
        __syncthreads();                                                      \
    } while (0)

    int v = 1;   // super-step counter; group base odd => compile-time parity
    for (; v + 3 <= nf; v += 4) {
        const float qf0 = (v + 4 <= nf) ? em[bF + (v + 4) * sV] : 0.f;
        const float qf1 = (v + 5 <= nf) ? em[bF + (v + 5) * sV] : 0.f;
        const float qf2 = (v + 6 <= nf) ? em[bF + (v + 6) * sV] : 0.f;
        const float qf3 = (v + 7 <= nf) ? em[bF + (v + 7) * sV] : 0.f;
        const float qb0 = (v + 4 <= nb) ? em[bB - (v + 4) * sV] : 0.f;
        const float qb1 = (v + 5 <= nb) ? em[bB - (v + 5) * sV] : 0.f;
        const float qb2 = (v + 6 <= nb) ? em[bB - (v + 6) * sV] : 0.f;
        const float qb3 = (v + 7 <= nb) ? em[bB - (v + 7) * sV] : 0.f;

        const float ef0 = __expf(pf0), eb0 = __expf(pb0);
        const float ef1 = __expf(pf1), eb1 = __expf(pb1);
        const float ef2 = __expf(pf2), eb2 = __expf(pb2);
        const float ef3 = __expf(pf3), eb3 = __expf(pb3);

        SSTEP(0, ef0, eb0, true);
        SSTEP(1, ef1, eb1, false);
        SSTEP(0, ef2, eb2, false);
        SSTEP(1, ef3, eb3, false);

        pf0 = qf0; pf1 = qf1; pf2 = qf2; pf3 = qf3;
        pb0 = qb0; pb1 = qb1; pb2 = qb2; pb3 = qb3;
    }
    // tail super-steps (guards block-uniform)
    if (v     <= nf) SSTEP(0, __expf(pf0), __expf(pb0), false);
    if (v + 1 <= nf) SSTEP(1, __expf(pf1), __expf(pb1), false);
    if (v + 2 <= nf) SSTEP(0, __expf(pf2), __expf(pb2), false);
#undef SSTEP

    // ---- extra bwd-only step if nb == nf + 1: advance U, freeze F ----
    if (nb > nf) {
        const int d = nb - v;   // which prefetch slot holds em for step nb
        const float pbx = (d == 0) ? pb0 : (d == 1) ? pb1
                        : (d == 2) ? pb2 : pb3;
        const float exb = __expf(pbx);
        const int pps = nf & 1;
        const __nv_bfloat162* __restrict__ e = shP[pps];
        const __nv_bfloat16 Fold = shP[pps][j].x;
        __nv_bfloat162 a0 = hz, a1 = hz, a2 = hz, a3 = hz;
#pragma unroll
        for (int i = 0; i < NT; i += 4) {
            a0 = __hfma2(e[i + 0], hT[i + 0], a0);
            a1 = __hfma2(e[i + 1], hT[i + 1], a1);
            a2 = __hfma2(e[i + 2], hT[i + 2], a2);
            a3 = __hfma2(e[i + 3], hT[i + 3], a3);
        }
        const __nv_bfloat162 s2 = __hadd2(__hadd2(a0, a1), __hadd2(a2, a3));
        const float2 f = __bfloat1622float2(s2);
        shP[pps ^ 1][j] =
            __halves2bfloat162(Fold, __float2bfloat16(f.y * exb));
        __syncthreads();
    }

    // ---- combine: Z = sum_j F_m(j) * u_m(j) * exp(-em_m(j)) ----
    {
        const float2 FU = __bfloat1622float2(shP[nb & 1][j]);
        float s = FU.x * FU.y * __expf(-em[m * sV + b * NT + j]);
#pragma unroll
        for (int o = 16; o > 0; o >>= 1)
            s += __shfl_xor_sync(0xffffffffu, s, o);
        if (lane == 0) sh_red[warp] = s;
        __syncthreads();

        if (j == 0) {
            const double denom = (double)(ktf + ktb) * 0.6931471805599453
                               + (double)logf(sh_red[0] + sh_red[1]);
            g_llh[b] = (float)((double)gnum - denom);
        }
    }

    // ---- final reduction by the last block ----
    __threadfence();
    if (j == 0)
        sh_flag = (atomicAdd(&g_done, 1) == BATCH - 1) ? 1 : 0;
    __syncthreads();

    if (sh_flag) {
        __shared__ double red[TPB];
        double acc = 0.0;
#pragma unroll
        for (int k = 0; k < BATCH / TPB; ++k)      // fixed order: 8 each
            acc += (double)g_llh[j + k * TPB];
        red[j] = acc;
        __syncthreads();
#pragma unroll
        for (int o = TPB / 2; o > 0; o >>= 1) {
            if (j < o) red[j] += red[j + o];
            __syncthreads();
        }
        if (j == 0) {
            out[0] = (float)red[0];
            atomicExch(&g_done, 0);    // reset for next replay
        }
    }
}

extern "C" void kernel_launch(void* const* d_in, const int* in_sizes, int n_in,
                              void* d_out, int out_size)
{
    const float* em     = (const float*)d_in[0];
    const void*  tags   = (const void*)d_in[1];
    const int*   mask   = (const int*)d_in[2];
    const float* startT = (const float*)d_in[3];
    const float* endT   = (const float*)d_in[4];
    const float* trans  = (const float*)d_in[5];
    float* out = (float*)d_out;

    crf_kernel<<<BATCH, TPB>>>(em, tags, mask, startT, endT, trans, out);
}